// round 16
// baseline (speedup 1.0000x reference)
#include <cuda_runtime.h>
#include <math.h>
#include <stdint.h>

#define EPSV 1e-5f

#define NB   4
#define CINC 128
#define CO   256
#define LATD 256
#define NG   16
#define NP_FULL 4096
#define NP_HALF 1024

__device__ float g_y[NB * CO * NP_FULL];
__device__ float g_yt[NB * CO * NP_FULL];
__device__ float g_qkv[NB * 2 * CO * NP_FULL];
__device__ float g_py[NB * CO * NP_HALF];
__device__ float g_px[NB * CINC * NP_HALF];
__device__ float g_sb[4096];

// ---------------- latent -> per-(b,ch) scale/bias -----------------------
__global__ void sb_kernel(const float* __restrict__ latent,
                          const float* __restrict__ lin_in,
                          const float* __restrict__ lin_out,
                          float* __restrict__ sb)
{
    int idx = blockIdx.x * blockDim.x + threadIdx.x;
    if (idx >= 4096) return;
    int which = idx >> 11;
    int b = (idx >> 9) & 3;
    int j = idx & 511;
    const float* lin = which ? lin_out : lin_in;
    const float* lt = latent + b * LATD;
    float acc = 0.f;
    #pragma unroll 4
    for (int l = 0; l < LATD; l++) acc += lt[l] * lin[j * LATD + l];
    sb[idx] = acc;
}

// ---------------- 64x64 plane transpose ----------------------------------
__global__ void transpose_kernel(const float* __restrict__ in,
                                 float* __restrict__ out)
{
    __shared__ float tile[32][33];
    int bc = blockIdx.z;
    int x0 = blockIdx.x * 32, y0 = blockIdx.y * 32;
    const float* p = in + (size_t)bc * 4096;
    float* q = out + (size_t)bc * 4096;
    int tx = threadIdx.x, ty = threadIdx.y;
    #pragma unroll
    for (int r = 0; r < 32; r += 8)
        tile[ty + r][tx] = p[(size_t)(y0 + ty + r) * 64 + x0 + tx];
    __syncthreads();
    #pragma unroll
    for (int r = 0; r < 32; r += 8)
        q[(size_t)(x0 + ty + r) * 64 + y0 + tx] = tile[tx][ty + r];
}

// ---------------- TF32 helpers -------------------------------------------
__device__ __forceinline__ void split_tf32(float v, uint32_t& hi, uint32_t& lo)
{
    uint32_t u = __float_as_uint(v) & 0xFFFFE000u;
    hi = u;
    lo = __float_as_uint(v - __uint_as_float(u));
}

__device__ __forceinline__ void mma_tf32(float* c, const uint32_t* a,
                                         uint32_t b0, uint32_t b1)
{
    asm volatile(
        "mma.sync.aligned.m16n8k8.row.col.f32.tf32.tf32.f32 "
        "{%0,%1,%2,%3}, {%4,%5,%6,%7}, {%8,%9}, {%0,%1,%2,%3};"
        : "+f"(c[0]), "+f"(c[1]), "+f"(c[2]), "+f"(c[3])
        : "r"(a[0]), "r"(a[1]), "r"(a[2]), "r"(a[3]), "r"(b0), "r"(b1));
}

// ---------------- tensor-core 1x1 conv (3xTF32, double-buffered) ---------
__global__ __launch_bounds__(256, 2)
void conv1x1_tc_kernel(const float* __restrict__ Wm,
                       const float* __restrict__ X,
                       float* __restrict__ Y,
                       int Cin, int Cout, int NP,
                       const float* __restrict__ bn,
                       const float* __restrict__ sb,
                       const float* __restrict__ alpha_ptr,
                       int mode)
{
    __shared__ float As[2][16][136];
    __shared__ float Bs[2][16][136];
    int tid = threadIdx.x;
    int b  = blockIdx.z;
    int o0 = blockIdx.y * 128;
    int p0 = blockIdx.x * 128;
    const float* Xb = X + (size_t)b * Cin * NP;

    int lane = tid & 31, warp = tid >> 5;
    int warp_m = warp & 1, warp_n = warp >> 1;
    int gid = lane >> 2, tig = lane & 3;

    int arow = tid >> 1;
    int akq  = (tid & 1) * 8;
    int bkr  = tid >> 4;
    int bn8  = (tid & 15) * 8;

    float4 pa0 = *(const float4*)&Wm[(size_t)(o0 + arow) * Cin + akq];
    float4 pa1 = *(const float4*)&Wm[(size_t)(o0 + arow) * Cin + akq + 4];
    float4 pb0 = *(const float4*)&Xb[(size_t)bkr * NP + p0 + bn8];
    float4 pb1 = *(const float4*)&Xb[(size_t)bkr * NP + p0 + bn8 + 4];

    float c[4][4][4];
    #pragma unroll
    for (int fm = 0; fm < 4; fm++)
        #pragma unroll
        for (int fn = 0; fn < 4; fn++)
            #pragma unroll
            for (int e = 0; e < 4; e++) c[fm][fn][e] = 0.f;

    As[0][akq + 0][arow] = pa0.x;
    As[0][akq + 1][arow] = pa0.y;
    As[0][akq + 2][arow] = pa0.z;
    As[0][akq + 3][arow] = pa0.w;
    As[0][akq + 4][arow] = pa1.x;
    As[0][akq + 5][arow] = pa1.y;
    As[0][akq + 6][arow] = pa1.z;
    As[0][akq + 7][arow] = pa1.w;
    *(float4*)&Bs[0][bkr][bn8] = pb0;
    *(float4*)&Bs[0][bkr][bn8 + 4] = pb1;
    __syncthreads();

    int nk = Cin >> 4;
    for (int kc = 0; kc < nk; kc++) {
        int cur = kc & 1;
        int nxt = cur ^ 1;
        bool have_next = (kc + 1 < nk);
        if (have_next) {
            int k0 = (kc + 1) << 4;
            pa0 = *(const float4*)&Wm[(size_t)(o0 + arow) * Cin + k0 + akq];
            pa1 = *(const float4*)&Wm[(size_t)(o0 + arow) * Cin + k0 + akq + 4];
            pb0 = *(const float4*)&Xb[(size_t)(k0 + bkr) * NP + p0 + bn8];
            pb1 = *(const float4*)&Xb[(size_t)(k0 + bkr) * NP + p0 + bn8 + 4];
        }
        #pragma unroll
        for (int ks = 0; ks < 2; ks++) {
            int kb = ks * 8;
            uint32_t bh[4][2], bl[4][2];
            #pragma unroll
            for (int fn = 0; fn < 4; fn++) {
                int n = warp_n * 32 + fn * 8 + gid;
                split_tf32(Bs[cur][kb + tig][n],     bh[fn][0], bl[fn][0]);
                split_tf32(Bs[cur][kb + tig + 4][n], bh[fn][1], bl[fn][1]);
            }
            #pragma unroll
            for (int fm = 0; fm < 4; fm++) {
                int m = warp_m * 64 + fm * 16 + gid;
                uint32_t ah[4], al[4];
                split_tf32(As[cur][kb + tig][m],         ah[0], al[0]);
                split_tf32(As[cur][kb + tig][m + 8],     ah[1], al[1]);
                split_tf32(As[cur][kb + tig + 4][m],     ah[2], al[2]);
                split_tf32(As[cur][kb + tig + 4][m + 8], ah[3], al[3]);
                #pragma unroll
                for (int fn = 0; fn < 4; fn++) {
                    mma_tf32(c[fm][fn], ah, bh[fn][0], bh[fn][1]);
                    mma_tf32(c[fm][fn], ah, bl[fn][0], bl[fn][1]);
                    mma_tf32(c[fm][fn], al, bh[fn][0], bh[fn][1]);
                }
            }
        }
        if (have_next) {
            As[nxt][akq + 0][arow] = pa0.x;
            As[nxt][akq + 1][arow] = pa0.y;
            As[nxt][akq + 2][arow] = pa0.z;
            As[nxt][akq + 3][arow] = pa0.w;
            As[nxt][akq + 4][arow] = pa1.x;
            As[nxt][akq + 5][arow] = pa1.y;
            As[nxt][akq + 6][arow] = pa1.z;
            As[nxt][akq + 7][arow] = pa1.w;
            *(float4*)&Bs[nxt][bkr][bn8] = pb0;
            *(float4*)&Bs[nxt][bkr][bn8 + 4] = pb1;
            __syncthreads();
        }
    }

    float alpha = (mode == 0) ? *alpha_ptr : 0.f;
    #pragma unroll
    for (int fm = 0; fm < 4; fm++) {
        int o_t = o0 + warp_m * 64 + fm * 16 + gid;
        int o_b = o_t + 8;
        float bsc_t = bn[o_t] * rsqrtf(bn[3 * Cout + o_t] + EPSV);
        float bbi_t = bn[Cout + o_t] - bn[2 * Cout + o_t] * bsc_t;
        float bsc_b = bn[o_b] * rsqrtf(bn[3 * Cout + o_b] + EPSV);
        float bbi_b = bn[Cout + o_b] - bn[2 * Cout + o_b] * bsc_b;
        float sl_t = 1.f, bl_t = 0.f, sl_b = 1.f, bl_b = 0.f;
        if (mode == 0) {
            sl_t = sb[b * 2 * Cout + o_t];
            bl_t = sb[b * 2 * Cout + Cout + o_t];
            sl_b = sb[b * 2 * Cout + o_b];
            bl_b = sb[b * 2 * Cout + Cout + o_b];
        }
        #pragma unroll
        for (int fn = 0; fn < 4; fn++) {
            int p = p0 + warp_n * 32 + fn * 8 + 2 * tig;
            float v0 = c[fm][fn][0] * bsc_t + bbi_t;
            float v1 = c[fm][fn][1] * bsc_t + bbi_t;
            float v2 = c[fm][fn][2] * bsc_b + bbi_b;
            float v3 = c[fm][fn][3] * bsc_b + bbi_b;
            if (mode == 0) {
                v0 = v0 * sl_t + bl_t; v0 = v0 > 0.f ? v0 : alpha * v0;
                v1 = v1 * sl_t + bl_t; v1 = v1 > 0.f ? v1 : alpha * v1;
                v2 = v2 * sl_b + bl_b; v2 = v2 > 0.f ? v2 : alpha * v2;
                v3 = v3 * sl_b + bl_b; v3 = v3 > 0.f ? v3 : alpha * v3;
            }
            float2 top; top.x = v0; top.y = v1;
            float2 bot; bot.x = v2; bot.y = v3;
            *(float2*)&Y[((size_t)(b * Cout + o_t)) * NP + p] = top;
            *(float2*)&Y[((size_t)(b * Cout + o_b)) * NP + p] = bot;
        }
    }
}

// ---------------- tensor-core FINAL (pooled inputs, cbn folded) ----------
__global__ __launch_bounds__(256, 2)
void final_tc_kernel(const float* __restrict__ Wo,
                     const float* __restrict__ py,
                     const float* __restrict__ Wr,
                     const float* __restrict__ px,
                     float* __restrict__ out,
                     const float* __restrict__ bn,
                     const float* __restrict__ sb,
                     const float* __restrict__ alpha_ptr)
{
    __shared__ float As[16][136];
    __shared__ float Bs[16][136];
    int tid = threadIdx.x;
    int b  = blockIdx.z;
    int o0 = blockIdx.y * 128;
    int p0 = blockIdx.x * 128;

    int lane = tid & 31, warp = tid >> 5;
    int warp_m = warp & 1, warp_n = warp >> 1;
    int gid = lane >> 2, tig = lane & 3;

    int arow = tid >> 1;
    int akq  = (tid & 1) * 8;
    int bkr  = tid >> 4;
    int bn8  = (tid & 15) * 8;

    int oa = o0 + arow;
    float scl;
    {
        float bsc = bn[oa] * rsqrtf(bn[768 + oa] + EPSV);
        scl = bsc * sb[b * 512 + oa];
    }

    float c[4][4][4];
    #pragma unroll
    for (int fm = 0; fm < 4; fm++)
        #pragma unroll
        for (int fn = 0; fn < 4; fn++)
            #pragma unroll
            for (int e = 0; e < 4; e++) c[fm][fn][e] = 0.f;

    #pragma unroll 1
    for (int phase = 0; phase < 2; phase++) {
        const float* Wm  = phase ? Wr : Wo;
        const float* Xb  = phase ? (px + (size_t)b * CINC * NP_HALF)
                                 : (py + (size_t)b * CO * NP_HALF);
        int Cin = phase ? CINC : CO;
        float asc = phase ? 1.f : scl;
        int nk = Cin >> 4;

        float4 pa0 = *(const float4*)&Wm[(size_t)oa * Cin + akq];
        float4 pa1 = *(const float4*)&Wm[(size_t)oa * Cin + akq + 4];
        float4 pb0 = *(const float4*)&Xb[(size_t)bkr * NP_HALF + p0 + bn8];
        float4 pb1 = *(const float4*)&Xb[(size_t)bkr * NP_HALF + p0 + bn8 + 4];

        for (int kc = 0; kc < nk; kc++) {
            As[akq + 0][arow] = pa0.x * asc;
            As[akq + 1][arow] = pa0.y * asc;
            As[akq + 2][arow] = pa0.z * asc;
            As[akq + 3][arow] = pa0.w * asc;
            As[akq + 4][arow] = pa1.x * asc;
            As[akq + 5][arow] = pa1.y * asc;
            As[akq + 6][arow] = pa1.z * asc;
            As[akq + 7][arow] = pa1.w * asc;
            *(float4*)&Bs[bkr][bn8] = pb0;
            *(float4*)&Bs[bkr][bn8 + 4] = pb1;
            __syncthreads();
            if (kc + 1 < nk) {
                int k0 = (kc + 1) << 4;
                pa0 = *(const float4*)&Wm[(size_t)oa * Cin + k0 + akq];
                pa1 = *(const float4*)&Wm[(size_t)oa * Cin + k0 + akq + 4];
                pb0 = *(const float4*)&Xb[(size_t)(k0 + bkr) * NP_HALF + p0 + bn8];
                pb1 = *(const float4*)&Xb[(size_t)(k0 + bkr) * NP_HALF + p0 + bn8 + 4];
            }
            #pragma unroll
            for (int ks = 0; ks < 2; ks++) {
                int kb = ks * 8;
                uint32_t bh[4][2], bl[4][2];
                #pragma unroll
                for (int fn = 0; fn < 4; fn++) {
                    int n = warp_n * 32 + fn * 8 + gid;
                    split_tf32(Bs[kb + tig][n],     bh[fn][0], bl[fn][0]);
                    split_tf32(Bs[kb + tig + 4][n], bh[fn][1], bl[fn][1]);
                }
                #pragma unroll
                for (int fm = 0; fm < 4; fm++) {
                    int m = warp_m * 64 + fm * 16 + gid;
                    uint32_t ah[4], al[4];
                    split_tf32(As[kb + tig][m],         ah[0], al[0]);
                    split_tf32(As[kb + tig][m + 8],     ah[1], al[1]);
                    split_tf32(As[kb + tig + 4][m],     ah[2], al[2]);
                    split_tf32(As[kb + tig + 4][m + 8], ah[3], al[3]);
                    #pragma unroll
                    for (int fn = 0; fn < 4; fn++) {
                        mma_tf32(c[fm][fn], ah, bh[fn][0], bh[fn][1]);
                        mma_tf32(c[fm][fn], ah, bl[fn][0], bl[fn][1]);
                        mma_tf32(c[fm][fn], al, bh[fn][0], bh[fn][1]);
                    }
                }
            }
            __syncthreads();
        }
    }

    float alpha = *alpha_ptr;
    #pragma unroll
    for (int fm = 0; fm < 4; fm++) {
        int o_t = o0 + warp_m * 64 + fm * 16 + gid;
        int o_b = o_t + 8;
        float bsc_t = bn[o_t] * rsqrtf(bn[768 + o_t] + EPSV);
        float bias_t = sb[b * 512 + o_t] * (bn[256 + o_t] - bn[512 + o_t] * bsc_t)
                     + sb[b * 512 + 256 + o_t];
        float bsc_b = bn[o_b] * rsqrtf(bn[768 + o_b] + EPSV);
        float bias_b = sb[b * 512 + o_b] * (bn[256 + o_b] - bn[512 + o_b] * bsc_b)
                     + sb[b * 512 + 256 + o_b];
        #pragma unroll
        for (int fn = 0; fn < 4; fn++) {
            int p = p0 + warp_n * 32 + fn * 8 + 2 * tig;
            float v0 = c[fm][fn][0] + bias_t;
            float v1 = c[fm][fn][1] + bias_t;
            float v2 = c[fm][fn][2] + bias_b;
            float v3 = c[fm][fn][3] + bias_b;
            v0 = v0 > 0.f ? v0 : alpha * v0;
            v1 = v1 > 0.f ? v1 : alpha * v1;
            v2 = v2 > 0.f ? v2 : alpha * v2;
            v3 = v3 > 0.f ? v3 : alpha * v3;
            float2 top; top.x = v0; top.y = v1;
            float2 bot; bot.x = v2; bot.y = v3;
            *(float2*)&out[((size_t)(b * CO + o_t)) * NP_HALF + p] = top;
            *(float2*)&out[((size_t)(b * CO + o_b)) * NP_HALF + p] = bot;
        }
    }
}

// ---------------- fused axial attention core (512 threads) ---------------
// ssim stride = 67 (odd) -> conflict-free scalar access with lanes varying i.
// Phase 5 j-split across both 256-thread halves; partials reduced via the
// (dead after phase 3) ske region.
#define OFF_SQ2  0
#define OFF_SV   1024
#define OFF_REL  2048
#define OFF_QE   6112
#define OFF_KE   10208
#define OFF_SIM  14304
#define OFF_SINV 18592
#define ATTN_SMEM_FLOATS 18656
#define ATTN_SMEM_BYTES (ATTN_SMEM_FLOATS * 4)
#define SIMP 67

__global__ __launch_bounds__(512)
void attn_kernel(const float* __restrict__ qkv,
                 float* __restrict__ out,
                 const float* __restrict__ rel,
                 const float* __restrict__ bns,
                 const float* __restrict__ bno)
{
    extern __shared__ float sm[];
    float* sq2  = sm + OFF_SQ2;
    float* svT  = sm + OFF_SV;
    float* srel = sm + OFF_REL;
    float* sqe  = sm + OFF_QE;
    float* ske  = sm + OFF_KE;
    float* ssim = sm + OFF_SIM;
    float* sinv = sm + OFF_SINV;

    int tid = threadIdx.x;
    int bn = blockIdx.x;
    int g  = blockIdx.y;
    int b  = bn >> 6, d1 = bn & 63;
    size_t base_off = (size_t)b * 512 * NP_FULL + (size_t)d1 * 64;

    #pragma unroll
    for (int i = tid; i < 2048; i += 512) {
        int u = i >> 6;
        int t = i & 63;
        float val = qkv[base_off + (size_t)(g * 32 + u) * NP_FULL + t];
        if (u < 16) sq2[u * 64 + t] = val;
        else        svT[t * 16 + (u - 16)] = val;
    }
    for (int i = tid; i < 1016; i += 512)
        *(float4*)&srel[i * 4] = *(const float4*)&rel[i * 4];
    __syncthreads();

    // ---- phase 2: diagonal-hoisted q_emb / k_emb ----
    {
        int D  = tid & 127;
        int tg = tid >> 7;
        float rq[8], rk[8];
        #pragma unroll
        for (int c = 0; c < 8; c++) {
            rq[c] = srel[c * 127 + D];
            rk[c] = srel[(8 + c) * 127 + D];
        }
        int dmj = 63 - D;
        #pragma unroll
        for (int m = 0; m < 4; m++) {
            int t0 = tg * 16 + m * 4;
            float aq0 = 0.f, aq1 = 0.f, aq2 = 0.f, aq3 = 0.f;
            float ak0 = 0.f, ak1 = 0.f, ak2 = 0.f, ak3 = 0.f;
            #pragma unroll
            for (int c = 0; c < 8; c++) {
                float4 q4 = *(const float4*)&sq2[c * 64 + t0];
                float4 k4 = *(const float4*)&sq2[(8 + c) * 64 + t0];
                aq0 += q4.x * rq[c]; aq1 += q4.y * rq[c];
                aq2 += q4.z * rq[c]; aq3 += q4.w * rq[c];
                ak0 += k4.x * rk[c]; ak1 += k4.y * rk[c];
                ak2 += k4.z * rk[c]; ak3 += k4.w * rk[c];
            }
            float aqv[4] = {aq0, aq1, aq2, aq3};
            float akv[4] = {ak0, ak1, ak2, ak3};
            #pragma unroll
            for (int u = 0; u < 4; u++) {
                int t = t0 + u;
                int j = t + dmj;
                if ((unsigned)j < 64u) {
                    sqe[t * 64 + j] = aqv[u];
                    ske[t * 64 + j] = akv[u];
                }
            }
        }
    }
    __syncthreads();

    float sA = bns[g]      * rsqrtf(bns[144 + g]      + EPSV);
    float sB = bns[16 + g] * rsqrtf(bns[144 + 16 + g] + EPSV);
    float sC = bns[32 + g] * rsqrtf(bns[144 + 32 + g] + EPSV);
    float tsum = (bns[48 + g]      - bns[96 + g]      * sA)
               + (bns[48 + 16 + g] - bns[96 + 16 + g] * sB)
               + (bns[48 + 32 + g] - bns[96 + 32 + g] * sC);

    // ---- phase 3: index-swapped 4x4 tiles (epilogue reads lane-contiguous)
    if (tid < 256) {
        int ti = tid & 15, tj = tid >> 4;
        float acc[4][4];
        #pragma unroll
        for (int u = 0; u < 4; u++)
            #pragma unroll
            for (int v = 0; v < 4; v++) acc[u][v] = 0.f;
        #pragma unroll 4
        for (int t = 0; t < 64; t++) {
            float4 qa = *(const float4*)&sqe[t * 64 + tj * 4];
            float4 kb = *(const float4*)&ske[t * 64 + ti * 4];
            float av[4] = {qa.x, qa.y, qa.z, qa.w};
            float bv[4] = {kb.x, kb.y, kb.z, kb.w};
            #pragma unroll
            for (int u = 0; u < 4; u++)
                #pragma unroll
                for (int v = 0; v < 4; v++) acc[u][v] += av[u] * bv[v];
        }
        #pragma unroll
        for (int u = 0; u < 4; u++) {
            int i = tj * 4 + u;
            float4 qe_i = *(const float4*)&sqe[i * 64 + ti * 4];
            float4 ke_i = *(const float4*)&ske[i * 64 + ti * 4];
            float qv[4] = {qe_i.x, qe_i.y, qe_i.z, qe_i.w};
            float kv[4] = {ke_i.x, ke_i.y, ke_i.z, ke_i.w};
            #pragma unroll
            for (int v = 0; v < 4; v++) {
                int j = ti * 4 + v;
                ssim[i * SIMP + j] = sA * acc[u][v] + sB * qv[v]
                                   + sC * kv[v] + tsum;
            }
        }
    }
    __syncthreads();

    // ---- phase 4: row max/exp/sum; store UNNORMALIZED exp + inv[i] ----
    {
        int r = tid >> 3, l = tid & 7;
        float m = -1e30f;
        #pragma unroll
        for (int jj = 0; jj < 8; jj++) m = fmaxf(m, ssim[r * SIMP + l + 8 * jj]);
        m = fmaxf(m, __shfl_xor_sync(0xffffffffu, m, 1));
        m = fmaxf(m, __shfl_xor_sync(0xffffffffu, m, 2));
        m = fmaxf(m, __shfl_xor_sync(0xffffffffu, m, 4));
        float ssum = 0.f;
        #pragma unroll
        for (int jj = 0; jj < 8; jj++) {
            int id = r * SIMP + l + 8 * jj;
            float e = __expf(ssim[id] - m);
            ssim[id] = e;
            ssum += e;
        }
        ssum += __shfl_xor_sync(0xffffffffu, ssum, 1);
        ssum += __shfl_xor_sync(0xffffffffu, ssum, 2);
        ssum += __shfl_xor_sync(0xffffffffu, ssum, 4);
        if (l == 0) sinv[r] = 1.f / ssum;
    }
    __syncthreads();

    // ---- phase 5: 512 threads, j-split halves, smem partial reduction ----
    {
        int pid = tid & 255;
        int i = pid & 63, cb = pid >> 6;
        int jh = tid >> 8;                 // 0: j 0..31, 1: j 32..63
        int c0 = 16 + cb * 4;
        float acca[4] = {0.f, 0.f, 0.f, 0.f};
        float acce[4] = {0.f, 0.f, 0.f, 0.f};
        int jbeg = jh * 32;
        #pragma unroll 4
        for (int j0 = jbeg; j0 < jbeg + 32; j0 += 4) {
            float sarr[4];
            sarr[0] = ssim[i * SIMP + j0];
            sarr[1] = ssim[i * SIMP + j0 + 1];
            sarr[2] = ssim[i * SIMP + j0 + 2];
            sarr[3] = ssim[i * SIMP + j0 + 3];
            #pragma unroll
            for (int e = 0; e < 4; e++) {
                int j = j0 + e;
                float s = sarr[e];
                int p = i - j + 63;
                float4 v4 = *(const float4*)&svT[j * 16 + cb * 4];
                float r0 = srel[(c0 + 0) * 127 + p];
                float r1 = srel[(c0 + 1) * 127 + p];
                float r2 = srel[(c0 + 2) * 127 + p];
                float r3 = srel[(c0 + 3) * 127 + p];
                acca[0] += s * v4.x;  acca[1] += s * v4.y;
                acca[2] += s * v4.z;  acca[3] += s * v4.w;
                acce[0] += s * r0;    acce[1] += s * r1;
                acce[2] += s * r2;    acce[3] += s * r3;
            }
        }
        // partials in the ske region (dead after phase 3), layout [e][pid]
        float* spart = ske;
        if (jh == 1) {
            #pragma unroll
            for (int e = 0; e < 4; e++) {
                spart[e * 256 + pid]       = acca[e];
                spart[(4 + e) * 256 + pid] = acce[e];
            }
        }
        __syncthreads();
        if (jh == 0) {
            #pragma unroll
            for (int e = 0; e < 4; e++) {
                acca[e] += spart[e * 256 + pid];
                acce[e] += spart[(4 + e) * 256 + pid];
            }
            float inv = sinv[i];
            #pragma unroll
            for (int cc = 0; cc < 4; cc++) {
                int c = cb * 4 + cc;
                int chA = g * 32 + 2 * c, chB = chA + 1;
                float sa = bno[chA] * rsqrtf(bno[1536 + chA] + EPSV);
                float ba = bno[512 + chA] - bno[1024 + chA] * sa;
                float sb2 = bno[chB] * rsqrtf(bno[1536 + chB] + EPSV);
                float bb2 = bno[512 + chB] - bno[1024 + chB] * sb2;
                float v = (acca[cc] * inv) * sa + ba + (acce[cc] * inv) * sb2 + bb2;
                int ch = g * 16 + c;
                out[((size_t)(b * CO + ch)) * NP_FULL + d1 * 64 + i] = v;
            }
        }
    }
}

// ---------------- 2x2 average pool --------------------------------------
__global__ void pool_kernel(const float* __restrict__ in, float* __restrict__ out, int C)
{
    int idx = blockIdx.x * blockDim.x + threadIdx.x;
    int total = NB * C * NP_HALF;
    if (idx >= total) return;
    int j = idx & 31;
    int i = (idx >> 5) & 31;
    int bc = idx >> 10;
    const float* p = in + (size_t)bc * NP_FULL + (size_t)(2 * i) * 64 + 2 * j;
    out[idx] = 0.25f * (p[0] + p[1] + p[64] + p[65]);
}

// ---------------- launcher ----------------------------------------------
extern "C" void kernel_launch(void* const* d_in, const int* in_sizes, int n_in,
                              void* d_out, int out_size)
{
    const float* x         = (const float*)d_in[0];
    const float* latent    = (const float*)d_in[1];
    const float* w_in      = (const float*)d_in[2];
    const float* bn_in     = (const float*)d_in[3];
    const float* lin_in    = (const float*)d_in[4];
    const float* alpha_in  = (const float*)d_in[5];
    const float* a0_wqkv   = (const float*)d_in[6];
    const float* a0_bn_qkv = (const float*)d_in[7];
    const float* a0_bn_sim = (const float*)d_in[8];
    const float* a0_bn_out = (const float*)d_in[9];
    const float* a0_rel    = (const float*)d_in[10];
    const float* a1_wqkv   = (const float*)d_in[11];
    const float* a1_bn_qkv = (const float*)d_in[12];
    const float* a1_bn_sim = (const float*)d_in[13];
    const float* a1_bn_out = (const float*)d_in[14];
    const float* a1_rel    = (const float*)d_in[15];
    const float* w_out     = (const float*)d_in[16];
    const float* bn_out    = (const float*)d_in[17];
    const float* lin_out   = (const float*)d_in[18];
    const float* w_res     = (const float*)d_in[19];
    const float* alpha_fin = (const float*)d_in[20];
    float* out = (float*)d_out;

    float *yb, *ytb, *qkvb, *pyb, *pxb, *sbb;
    cudaGetSymbolAddress((void**)&yb,   g_y);
    cudaGetSymbolAddress((void**)&ytb,  g_yt);
    cudaGetSymbolAddress((void**)&qkvb, g_qkv);
    cudaGetSymbolAddress((void**)&pyb,  g_py);
    cudaGetSymbolAddress((void**)&pxb,  g_px);
    cudaGetSymbolAddress((void**)&sbb,  g_sb);

    cudaFuncSetAttribute(attn_kernel, cudaFuncAttributeMaxDynamicSharedMemorySize,
                         ATTN_SMEM_BYTES);

    dim3 tgrid(2, 2, NB * CO);
    dim3 tblk(32, 8);

    // 1. latent-conditioned scale/bias
    sb_kernel<<<16, 256>>>(latent, lin_in, lin_out, sbb);

    // 2. y = prelu(cbn(conv1x1(w_in, x)))
    {
        dim3 g(NP_FULL / 128, CO / 128, NB);
        conv1x1_tc_kernel<<<g, 256>>>(w_in, x, yb, CINC, CO, NP_FULL,
                                      bn_in, sbb, alpha_in, 0);
    }

    // 3. transpose; qkv conv a0; attn0
    transpose_kernel<<<tgrid, tblk>>>(yb, ytb);
    {
        dim3 g(NP_FULL / 128, (2 * CO) / 128, NB);
        conv1x1_tc_kernel<<<g, 256>>>(a0_wqkv, ytb, qkvb, CO, 2 * CO, NP_FULL,
                                      a0_bn_qkv, nullptr, nullptr, 1);
        dim3 ga(256, NG);
        attn_kernel<<<ga, 512, ATTN_SMEM_BYTES>>>(qkvb, yb, a0_rel,
                                                  a0_bn_sim, a0_bn_out);
    }

    // 4. transpose; qkv conv a1; attn1
    transpose_kernel<<<tgrid, tblk>>>(yb, ytb);
    {
        dim3 g(NP_FULL / 128, (2 * CO) / 128, NB);
        conv1x1_tc_kernel<<<g, 256>>>(a1_wqkv, ytb, qkvb, CO, 2 * CO, NP_FULL,
                                      a1_bn_qkv, nullptr, nullptr, 1);
        dim3 ga(256, NG);
        attn_kernel<<<ga, 512, ATTN_SMEM_BYTES>>>(qkvb, yb, a1_rel,
                                                  a1_bn_sim, a1_bn_out);
    }

    // 5. pools
    pool_kernel<<<(NB * CO * NP_HALF + 255) / 256, 256>>>(yb, pyb, CO);
    pool_kernel<<<(NB * CINC * NP_HALF + 255) / 256, 256>>>(x, pxb, CINC);

    // 6. final (tensor-core, cbn folded into A, pooled inputs)
    {
        dim3 g(NP_HALF / 128, CO / 128, NB);
        final_tc_kernel<<<g, 256>>>(w_out, pyb, w_res, pxb, out,
                                    bn_out, sbb + 2048, alpha_fin);
    }
}

// round 17
// speedup vs baseline: 1.0126x; 1.0126x over previous
#include <cuda_runtime.h>
#include <math.h>
#include <stdint.h>

#define EPSV 1e-5f

#define NB   4
#define CINC 128
#define CO   256
#define LATD 256
#define NG   16
#define NP_FULL 4096
#define NP_HALF 1024

__device__ float g_y[NB * CO * NP_FULL];
__device__ float g_yt[NB * CO * NP_FULL];
__device__ float g_qkv[NB * 2 * CO * NP_FULL];
__device__ float g_py[NB * CO * NP_HALF];
__device__ float g_px[NB * CINC * NP_HALF];
__device__ float g_sb[4096];

// ---------------- latent -> per-(b,ch) scale/bias -----------------------
__global__ void sb_kernel(const float* __restrict__ latent,
                          const float* __restrict__ lin_in,
                          const float* __restrict__ lin_out,
                          float* __restrict__ sb)
{
    int idx = blockIdx.x * blockDim.x + threadIdx.x;
    if (idx >= 4096) return;
    int which = idx >> 11;
    int b = (idx >> 9) & 3;
    int j = idx & 511;
    const float* lin = which ? lin_out : lin_in;
    const float* lt = latent + b * LATD;
    float acc = 0.f;
    #pragma unroll 4
    for (int l = 0; l < LATD; l++) acc += lt[l] * lin[j * LATD + l];
    sb[idx] = acc;
}

// ---------------- 64x64 plane transpose ----------------------------------
__global__ void transpose_kernel(const float* __restrict__ in,
                                 float* __restrict__ out)
{
    __shared__ float tile[32][33];
    int bc = blockIdx.z;
    int x0 = blockIdx.x * 32, y0 = blockIdx.y * 32;
    const float* p = in + (size_t)bc * 4096;
    float* q = out + (size_t)bc * 4096;
    int tx = threadIdx.x, ty = threadIdx.y;
    #pragma unroll
    for (int r = 0; r < 32; r += 8)
        tile[ty + r][tx] = p[(size_t)(y0 + ty + r) * 64 + x0 + tx];
    __syncthreads();
    #pragma unroll
    for (int r = 0; r < 32; r += 8)
        q[(size_t)(x0 + ty + r) * 64 + y0 + tx] = tile[tx][ty + r];
}

// ---------------- TF32 helpers -------------------------------------------
__device__ __forceinline__ void split_tf32(float v, uint32_t& hi, uint32_t& lo)
{
    uint32_t u = __float_as_uint(v) & 0xFFFFE000u;
    hi = u;
    lo = __float_as_uint(v - __uint_as_float(u));
}

__device__ __forceinline__ void mma_tf32(float* c, const uint32_t* a,
                                         uint32_t b0, uint32_t b1)
{
    asm volatile(
        "mma.sync.aligned.m16n8k8.row.col.f32.tf32.tf32.f32 "
        "{%0,%1,%2,%3}, {%4,%5,%6,%7}, {%8,%9}, {%0,%1,%2,%3};"
        : "+f"(c[0]), "+f"(c[1]), "+f"(c[2]), "+f"(c[3])
        : "r"(a[0]), "r"(a[1]), "r"(a[2]), "r"(a[3]), "r"(b0), "r"(b1));
}

// ---------------- tensor-core 1x1 conv (3xTF32, double-buffered) ---------
// MMA order: per fm, sweep fn for hi*hi, then hi*lo, then lo*hi -> each
// accumulator's 3-MMA RAW chain interleaved with 3 independent MMAs.
__global__ __launch_bounds__(256, 2)
void conv1x1_tc_kernel(const float* __restrict__ Wm,
                       const float* __restrict__ X,
                       float* __restrict__ Y,
                       int Cin, int Cout, int NP,
                       const float* __restrict__ bn,
                       const float* __restrict__ sb,
                       const float* __restrict__ alpha_ptr,
                       int mode)
{
    __shared__ float As[2][16][136];
    __shared__ float Bs[2][16][136];
    int tid = threadIdx.x;
    int b  = blockIdx.z;
    int o0 = blockIdx.y * 128;
    int p0 = blockIdx.x * 128;
    const float* Xb = X + (size_t)b * Cin * NP;

    int lane = tid & 31, warp = tid >> 5;
    int warp_m = warp & 1, warp_n = warp >> 1;
    int gid = lane >> 2, tig = lane & 3;

    int arow = tid >> 1;
    int akq  = (tid & 1) * 8;
    int bkr  = tid >> 4;
    int bn8  = (tid & 15) * 8;

    float4 pa0 = *(const float4*)&Wm[(size_t)(o0 + arow) * Cin + akq];
    float4 pa1 = *(const float4*)&Wm[(size_t)(o0 + arow) * Cin + akq + 4];
    float4 pb0 = *(const float4*)&Xb[(size_t)bkr * NP + p0 + bn8];
    float4 pb1 = *(const float4*)&Xb[(size_t)bkr * NP + p0 + bn8 + 4];

    float c[4][4][4];
    #pragma unroll
    for (int fm = 0; fm < 4; fm++)
        #pragma unroll
        for (int fn = 0; fn < 4; fn++)
            #pragma unroll
            for (int e = 0; e < 4; e++) c[fm][fn][e] = 0.f;

    As[0][akq + 0][arow] = pa0.x;
    As[0][akq + 1][arow] = pa0.y;
    As[0][akq + 2][arow] = pa0.z;
    As[0][akq + 3][arow] = pa0.w;
    As[0][akq + 4][arow] = pa1.x;
    As[0][akq + 5][arow] = pa1.y;
    As[0][akq + 6][arow] = pa1.z;
    As[0][akq + 7][arow] = pa1.w;
    *(float4*)&Bs[0][bkr][bn8] = pb0;
    *(float4*)&Bs[0][bkr][bn8 + 4] = pb1;
    __syncthreads();

    int nk = Cin >> 4;
    for (int kc = 0; kc < nk; kc++) {
        int cur = kc & 1;
        int nxt = cur ^ 1;
        bool have_next = (kc + 1 < nk);
        if (have_next) {
            int k0 = (kc + 1) << 4;
            pa0 = *(const float4*)&Wm[(size_t)(o0 + arow) * Cin + k0 + akq];
            pa1 = *(const float4*)&Wm[(size_t)(o0 + arow) * Cin + k0 + akq + 4];
            pb0 = *(const float4*)&Xb[(size_t)(k0 + bkr) * NP + p0 + bn8];
            pb1 = *(const float4*)&Xb[(size_t)(k0 + bkr) * NP + p0 + bn8 + 4];
        }
        #pragma unroll
        for (int ks = 0; ks < 2; ks++) {
            int kb = ks * 8;
            uint32_t bh[4][2], bl[4][2];
            #pragma unroll
            for (int fn = 0; fn < 4; fn++) {
                int n = warp_n * 32 + fn * 8 + gid;
                split_tf32(Bs[cur][kb + tig][n],     bh[fn][0], bl[fn][0]);
                split_tf32(Bs[cur][kb + tig + 4][n], bh[fn][1], bl[fn][1]);
            }
            #pragma unroll
            for (int fm = 0; fm < 4; fm++) {
                int m = warp_m * 64 + fm * 16 + gid;
                uint32_t ah[4], al[4];
                split_tf32(As[cur][kb + tig][m],         ah[0], al[0]);
                split_tf32(As[cur][kb + tig][m + 8],     ah[1], al[1]);
                split_tf32(As[cur][kb + tig + 4][m],     ah[2], al[2]);
                split_tf32(As[cur][kb + tig + 4][m + 8], ah[3], al[3]);
                #pragma unroll
                for (int fn = 0; fn < 4; fn++)
                    mma_tf32(c[fm][fn], ah, bh[fn][0], bh[fn][1]);
                #pragma unroll
                for (int fn = 0; fn < 4; fn++)
                    mma_tf32(c[fm][fn], ah, bl[fn][0], bl[fn][1]);
                #pragma unroll
                for (int fn = 0; fn < 4; fn++)
                    mma_tf32(c[fm][fn], al, bh[fn][0], bh[fn][1]);
            }
        }
        if (have_next) {
            As[nxt][akq + 0][arow] = pa0.x;
            As[nxt][akq + 1][arow] = pa0.y;
            As[nxt][akq + 2][arow] = pa0.z;
            As[nxt][akq + 3][arow] = pa0.w;
            As[nxt][akq + 4][arow] = pa1.x;
            As[nxt][akq + 5][arow] = pa1.y;
            As[nxt][akq + 6][arow] = pa1.z;
            As[nxt][akq + 7][arow] = pa1.w;
            *(float4*)&Bs[nxt][bkr][bn8] = pb0;
            *(float4*)&Bs[nxt][bkr][bn8 + 4] = pb1;
            __syncthreads();
        }
    }

    float alpha = (mode == 0) ? *alpha_ptr : 0.f;
    #pragma unroll
    for (int fm = 0; fm < 4; fm++) {
        int o_t = o0 + warp_m * 64 + fm * 16 + gid;
        int o_b = o_t + 8;
        float bsc_t = bn[o_t] * rsqrtf(bn[3 * Cout + o_t] + EPSV);
        float bbi_t = bn[Cout + o_t] - bn[2 * Cout + o_t] * bsc_t;
        float bsc_b = bn[o_b] * rsqrtf(bn[3 * Cout + o_b] + EPSV);
        float bbi_b = bn[Cout + o_b] - bn[2 * Cout + o_b] * bsc_b;
        float sl_t = 1.f, bl_t = 0.f, sl_b = 1.f, bl_b = 0.f;
        if (mode == 0) {
            sl_t = sb[b * 2 * Cout + o_t];
            bl_t = sb[b * 2 * Cout + Cout + o_t];
            sl_b = sb[b * 2 * Cout + o_b];
            bl_b = sb[b * 2 * Cout + Cout + o_b];
        }
        #pragma unroll
        for (int fn = 0; fn < 4; fn++) {
            int p = p0 + warp_n * 32 + fn * 8 + 2 * tig;
            float v0 = c[fm][fn][0] * bsc_t + bbi_t;
            float v1 = c[fm][fn][1] * bsc_t + bbi_t;
            float v2 = c[fm][fn][2] * bsc_b + bbi_b;
            float v3 = c[fm][fn][3] * bsc_b + bbi_b;
            if (mode == 0) {
                v0 = v0 * sl_t + bl_t; v0 = v0 > 0.f ? v0 : alpha * v0;
                v1 = v1 * sl_t + bl_t; v1 = v1 > 0.f ? v1 : alpha * v1;
                v2 = v2 * sl_b + bl_b; v2 = v2 > 0.f ? v2 : alpha * v2;
                v3 = v3 * sl_b + bl_b; v3 = v3 > 0.f ? v3 : alpha * v3;
            }
            float2 top; top.x = v0; top.y = v1;
            float2 bot; bot.x = v2; bot.y = v3;
            *(float2*)&Y[((size_t)(b * Cout + o_t)) * NP + p] = top;
            *(float2*)&Y[((size_t)(b * Cout + o_b)) * NP + p] = bot;
        }
    }
}

// ---------------- tensor-core FINAL (pooled inputs, cbn folded) ----------
__global__ __launch_bounds__(256, 2)
void final_tc_kernel(const float* __restrict__ Wo,
                     const float* __restrict__ py,
                     const float* __restrict__ Wr,
                     const float* __restrict__ px,
                     float* __restrict__ out,
                     const float* __restrict__ bn,
                     const float* __restrict__ sb,
                     const float* __restrict__ alpha_ptr)
{
    __shared__ float As[16][136];
    __shared__ float Bs[16][136];
    int tid = threadIdx.x;
    int b  = blockIdx.z;
    int o0 = blockIdx.y * 128;
    int p0 = blockIdx.x * 128;

    int lane = tid & 31, warp = tid >> 5;
    int warp_m = warp & 1, warp_n = warp >> 1;
    int gid = lane >> 2, tig = lane & 3;

    int arow = tid >> 1;
    int akq  = (tid & 1) * 8;
    int bkr  = tid >> 4;
    int bn8  = (tid & 15) * 8;

    int oa = o0 + arow;
    float scl;
    {
        float bsc = bn[oa] * rsqrtf(bn[768 + oa] + EPSV);
        scl = bsc * sb[b * 512 + oa];
    }

    float c[4][4][4];
    #pragma unroll
    for (int fm = 0; fm < 4; fm++)
        #pragma unroll
        for (int fn = 0; fn < 4; fn++)
            #pragma unroll
            for (int e = 0; e < 4; e++) c[fm][fn][e] = 0.f;

    #pragma unroll 1
    for (int phase = 0; phase < 2; phase++) {
        const float* Wm  = phase ? Wr : Wo;
        const float* Xb  = phase ? (px + (size_t)b * CINC * NP_HALF)
                                 : (py + (size_t)b * CO * NP_HALF);
        int Cin = phase ? CINC : CO;
        float asc = phase ? 1.f : scl;
        int nk = Cin >> 4;

        float4 pa0 = *(const float4*)&Wm[(size_t)oa * Cin + akq];
        float4 pa1 = *(const float4*)&Wm[(size_t)oa * Cin + akq + 4];
        float4 pb0 = *(const float4*)&Xb[(size_t)bkr * NP_HALF + p0 + bn8];
        float4 pb1 = *(const float4*)&Xb[(size_t)bkr * NP_HALF + p0 + bn8 + 4];

        for (int kc = 0; kc < nk; kc++) {
            As[akq + 0][arow] = pa0.x * asc;
            As[akq + 1][arow] = pa0.y * asc;
            As[akq + 2][arow] = pa0.z * asc;
            As[akq + 3][arow] = pa0.w * asc;
            As[akq + 4][arow] = pa1.x * asc;
            As[akq + 5][arow] = pa1.y * asc;
            As[akq + 6][arow] = pa1.z * asc;
            As[akq + 7][arow] = pa1.w * asc;
            *(float4*)&Bs[bkr][bn8] = pb0;
            *(float4*)&Bs[bkr][bn8 + 4] = pb1;
            __syncthreads();
            if (kc + 1 < nk) {
                int k0 = (kc + 1) << 4;
                pa0 = *(const float4*)&Wm[(size_t)oa * Cin + k0 + akq];
                pa1 = *(const float4*)&Wm[(size_t)oa * Cin + k0 + akq + 4];
                pb0 = *(const float4*)&Xb[(size_t)(k0 + bkr) * NP_HALF + p0 + bn8];
                pb1 = *(const float4*)&Xb[(size_t)(k0 + bkr) * NP_HALF + p0 + bn8 + 4];
            }
            #pragma unroll
            for (int ks = 0; ks < 2; ks++) {
                int kb = ks * 8;
                uint32_t bh[4][2], bl[4][2];
                #pragma unroll
                for (int fn = 0; fn < 4; fn++) {
                    int n = warp_n * 32 + fn * 8 + gid;
                    split_tf32(Bs[kb + tig][n],     bh[fn][0], bl[fn][0]);
                    split_tf32(Bs[kb + tig + 4][n], bh[fn][1], bl[fn][1]);
                }
                #pragma unroll
                for (int fm = 0; fm < 4; fm++) {
                    int m = warp_m * 64 + fm * 16 + gid;
                    uint32_t ah[4], al[4];
                    split_tf32(As[kb + tig][m],         ah[0], al[0]);
                    split_tf32(As[kb + tig][m + 8],     ah[1], al[1]);
                    split_tf32(As[kb + tig + 4][m],     ah[2], al[2]);
                    split_tf32(As[kb + tig + 4][m + 8], ah[3], al[3]);
                    #pragma unroll
                    for (int fn = 0; fn < 4; fn++)
                        mma_tf32(c[fm][fn], ah, bh[fn][0], bh[fn][1]);
                    #pragma unroll
                    for (int fn = 0; fn < 4; fn++)
                        mma_tf32(c[fm][fn], ah, bl[fn][0], bl[fn][1]);
                    #pragma unroll
                    for (int fn = 0; fn < 4; fn++)
                        mma_tf32(c[fm][fn], al, bh[fn][0], bh[fn][1]);
                }
            }
            __syncthreads();
        }
    }

    float alpha = *alpha_ptr;
    #pragma unroll
    for (int fm = 0; fm < 4; fm++) {
        int o_t = o0 + warp_m * 64 + fm * 16 + gid;
        int o_b = o_t + 8;
        float bsc_t = bn[o_t] * rsqrtf(bn[768 + o_t] + EPSV);
        float bias_t = sb[b * 512 + o_t] * (bn[256 + o_t] - bn[512 + o_t] * bsc_t)
                     + sb[b * 512 + 256 + o_t];
        float bsc_b = bn[o_b] * rsqrtf(bn[768 + o_b] + EPSV);
        float bias_b = sb[b * 512 + o_b] * (bn[256 + o_b] - bn[512 + o_b] * bsc_b)
                     + sb[b * 512 + 256 + o_b];
        #pragma unroll
        for (int fn = 0; fn < 4; fn++) {
            int p = p0 + warp_n * 32 + fn * 8 + 2 * tig;
            float v0 = c[fm][fn][0] + bias_t;
            float v1 = c[fm][fn][1] + bias_t;
            float v2 = c[fm][fn][2] + bias_b;
            float v3 = c[fm][fn][3] + bias_b;
            v0 = v0 > 0.f ? v0 : alpha * v0;
            v1 = v1 > 0.f ? v1 : alpha * v1;
            v2 = v2 > 0.f ? v2 : alpha * v2;
            v3 = v3 > 0.f ? v3 : alpha * v3;
            float2 top; top.x = v0; top.y = v1;
            float2 bot; bot.x = v2; bot.y = v3;
            *(float2*)&out[((size_t)(b * CO + o_t)) * NP_HALF + p] = top;
            *(float2*)&out[((size_t)(b * CO + o_b)) * NP_HALF + p] = bot;
        }
    }
}

// ---------------- fused axial attention core (512 threads) ---------------
// R14 version: phase 5 with 256 threads (crossbar-byte floor; j-split refuted).
#define OFF_SQ2  0
#define OFF_SV   1024
#define OFF_REL  2048
#define OFF_QE   6112
#define OFF_KE   10208
#define OFF_SIM  14304
#define OFF_SINV 18592
#define ATTN_SMEM_FLOATS 18656
#define ATTN_SMEM_BYTES (ATTN_SMEM_FLOATS * 4)
#define SIMP 67

__global__ __launch_bounds__(512)
void attn_kernel(const float* __restrict__ qkv,
                 float* __restrict__ out,
                 const float* __restrict__ rel,
                 const float* __restrict__ bns,
                 const float* __restrict__ bno)
{
    extern __shared__ float sm[];
    float* sq2  = sm + OFF_SQ2;
    float* svT  = sm + OFF_SV;
    float* srel = sm + OFF_REL;
    float* sqe  = sm + OFF_QE;
    float* ske  = sm + OFF_KE;
    float* ssim = sm + OFF_SIM;
    float* sinv = sm + OFF_SINV;

    int tid = threadIdx.x;
    int bn = blockIdx.x;
    int g  = blockIdx.y;
    int b  = bn >> 6, d1 = bn & 63;
    size_t base_off = (size_t)b * 512 * NP_FULL + (size_t)d1 * 64;

    #pragma unroll
    for (int i = tid; i < 2048; i += 512) {
        int u = i >> 6;
        int t = i & 63;
        float val = qkv[base_off + (size_t)(g * 32 + u) * NP_FULL + t];
        if (u < 16) sq2[u * 64 + t] = val;
        else        svT[t * 16 + (u - 16)] = val;
    }
    for (int i = tid; i < 1016; i += 512)
        *(float4*)&srel[i * 4] = *(const float4*)&rel[i * 4];
    __syncthreads();

    // ---- phase 2: diagonal-hoisted q_emb / k_emb ----
    {
        int D  = tid & 127;
        int tg = tid >> 7;
        float rq[8], rk[8];
        #pragma unroll
        for (int c = 0; c < 8; c++) {
            rq[c] = srel[c * 127 + D];
            rk[c] = srel[(8 + c) * 127 + D];
        }
        int dmj = 63 - D;
        #pragma unroll
        for (int m = 0; m < 4; m++) {
            int t0 = tg * 16 + m * 4;
            float aq0 = 0.f, aq1 = 0.f, aq2 = 0.f, aq3 = 0.f;
            float ak0 = 0.f, ak1 = 0.f, ak2 = 0.f, ak3 = 0.f;
            #pragma unroll
            for (int c = 0; c < 8; c++) {
                float4 q4 = *(const float4*)&sq2[c * 64 + t0];
                float4 k4 = *(const float4*)&sq2[(8 + c) * 64 + t0];
                aq0 += q4.x * rq[c]; aq1 += q4.y * rq[c];
                aq2 += q4.z * rq[c]; aq3 += q4.w * rq[c];
                ak0 += k4.x * rk[c]; ak1 += k4.y * rk[c];
                ak2 += k4.z * rk[c]; ak3 += k4.w * rk[c];
            }
            float aqv[4] = {aq0, aq1, aq2, aq3};
            float akv[4] = {ak0, ak1, ak2, ak3};
            #pragma unroll
            for (int u = 0; u < 4; u++) {
                int t = t0 + u;
                int j = t + dmj;
                if ((unsigned)j < 64u) {
                    sqe[t * 64 + j] = aqv[u];
                    ske[t * 64 + j] = akv[u];
                }
            }
        }
    }
    __syncthreads();

    float sA = bns[g]      * rsqrtf(bns[144 + g]      + EPSV);
    float sB = bns[16 + g] * rsqrtf(bns[144 + 16 + g] + EPSV);
    float sC = bns[32 + g] * rsqrtf(bns[144 + 32 + g] + EPSV);
    float tsum = (bns[48 + g]      - bns[96 + g]      * sA)
               + (bns[48 + 16 + g] - bns[96 + 16 + g] * sB)
               + (bns[48 + 32 + g] - bns[96 + 32 + g] * sC);

    // ---- phase 3: index-swapped 4x4 tiles ----
    if (tid < 256) {
        int ti = tid & 15, tj = tid >> 4;
        float acc[4][4];
        #pragma unroll
        for (int u = 0; u < 4; u++)
            #pragma unroll
            for (int v = 0; v < 4; v++) acc[u][v] = 0.f;
        #pragma unroll 4
        for (int t = 0; t < 64; t++) {
            float4 qa = *(const float4*)&sqe[t * 64 + tj * 4];
            float4 kb = *(const float4*)&ske[t * 64 + ti * 4];
            float av[4] = {qa.x, qa.y, qa.z, qa.w};
            float bv[4] = {kb.x, kb.y, kb.z, kb.w};
            #pragma unroll
            for (int u = 0; u < 4; u++)
                #pragma unroll
                for (int v = 0; v < 4; v++) acc[u][v] += av[u] * bv[v];
        }
        #pragma unroll
        for (int u = 0; u < 4; u++) {
            int i = tj * 4 + u;
            float4 qe_i = *(const float4*)&sqe[i * 64 + ti * 4];
            float4 ke_i = *(const float4*)&ske[i * 64 + ti * 4];
            float qv[4] = {qe_i.x, qe_i.y, qe_i.z, qe_i.w};
            float kv[4] = {ke_i.x, ke_i.y, ke_i.z, ke_i.w};
            #pragma unroll
            for (int v = 0; v < 4; v++) {
                int j = ti * 4 + v;
                ssim[i * SIMP + j] = sA * acc[u][v] + sB * qv[v]
                                   + sC * kv[v] + tsum;
            }
        }
    }
    __syncthreads();

    // ---- phase 4: row max/exp/sum; store UNNORMALIZED exp + inv[i] ----
    {
        int r = tid >> 3, l = tid & 7;
        float m = -1e30f;
        #pragma unroll
        for (int jj = 0; jj < 8; jj++) m = fmaxf(m, ssim[r * SIMP + l + 8 * jj]);
        m = fmaxf(m, __shfl_xor_sync(0xffffffffu, m, 1));
        m = fmaxf(m, __shfl_xor_sync(0xffffffffu, m, 2));
        m = fmaxf(m, __shfl_xor_sync(0xffffffffu, m, 4));
        float ssum = 0.f;
        #pragma unroll
        for (int jj = 0; jj < 8; jj++) {
            int id = r * SIMP + l + 8 * jj;
            float e = __expf(ssim[id] - m);
            ssim[id] = e;
            ssum += e;
        }
        ssum += __shfl_xor_sync(0xffffffffu, ssum, 1);
        ssum += __shfl_xor_sync(0xffffffffu, ssum, 2);
        ssum += __shfl_xor_sync(0xffffffffu, ssum, 4);
        if (l == 0) sinv[r] = 1.f / ssum;
    }
    __syncthreads();

    // ---- phase 5: 256 threads, 4 channels; scalar ssim reads (odd stride)
    if (tid < 256) {
        int i = tid & 63, cb = tid >> 6;
        int c0 = 16 + cb * 4;
        float acca[4] = {0.f, 0.f, 0.f, 0.f};
        float acce[4] = {0.f, 0.f, 0.f, 0.f};
        #pragma unroll 4
        for (int j0 = 0; j0 < 64; j0 += 4) {
            float sarr[4];
            sarr[0] = ssim[i * SIMP + j0];
            sarr[1] = ssim[i * SIMP + j0 + 1];
            sarr[2] = ssim[i * SIMP + j0 + 2];
            sarr[3] = ssim[i * SIMP + j0 + 3];
            #pragma unroll
            for (int e = 0; e < 4; e++) {
                int j = j0 + e;
                float s = sarr[e];
                int p = i - j + 63;
                float4 v4 = *(const float4*)&svT[j * 16 + cb * 4];
                float r0 = srel[(c0 + 0) * 127 + p];
                float r1 = srel[(c0 + 1) * 127 + p];
                float r2 = srel[(c0 + 2) * 127 + p];
                float r3 = srel[(c0 + 3) * 127 + p];
                acca[0] += s * v4.x;  acca[1] += s * v4.y;
                acca[2] += s * v4.z;  acca[3] += s * v4.w;
                acce[0] += s * r0;    acce[1] += s * r1;
                acce[2] += s * r2;    acce[3] += s * r3;
            }
        }
        float inv = sinv[i];
        #pragma unroll
        for (int cc = 0; cc < 4; cc++) {
            int c = cb * 4 + cc;
            int chA = g * 32 + 2 * c, chB = chA + 1;
            float sa = bno[chA] * rsqrtf(bno[1536 + chA] + EPSV);
            float ba = bno[512 + chA] - bno[1024 + chA] * sa;
            float sb2 = bno[chB] * rsqrtf(bno[1536 + chB] + EPSV);
            float bb2 = bno[512 + chB] - bno[1024 + chB] * sb2;
            float v = (acca[cc] * inv) * sa + ba + (acce[cc] * inv) * sb2 + bb2;
            int ch = g * 16 + c;
            out[((size_t)(b * CO + ch)) * NP_FULL + d1 * 64 + i] = v;
        }
    }
}

// ---------------- merged 2x2 average pool (y -> py, x -> px) -------------
#define POOL_Y_TOTAL (NB * CO * NP_HALF)
#define POOL_TOTAL   (NB * (CO + CINC) * NP_HALF)
__global__ void pool2_kernel(const float* __restrict__ yin, float* __restrict__ yout,
                             const float* __restrict__ xin, float* __restrict__ xout)
{
    int idx = blockIdx.x * blockDim.x + threadIdx.x;
    if (idx >= POOL_TOTAL) return;
    const float* in;
    float* outp;
    int lidx;
    if (idx < POOL_Y_TOTAL) { in = yin; outp = yout; lidx = idx; }
    else { in = xin; outp = xout; lidx = idx - POOL_Y_TOTAL; }
    int j = lidx & 31;
    int i = (lidx >> 5) & 31;
    int bc = lidx >> 10;
    const float* p = in + (size_t)bc * NP_FULL + (size_t)(2 * i) * 64 + 2 * j;
    outp[lidx] = 0.25f * (p[0] + p[1] + p[64] + p[65]);
}

// ---------------- launcher ----------------------------------------------
extern "C" void kernel_launch(void* const* d_in, const int* in_sizes, int n_in,
                              void* d_out, int out_size)
{
    const float* x         = (const float*)d_in[0];
    const float* latent    = (const float*)d_in[1];
    const float* w_in      = (const float*)d_in[2];
    const float* bn_in     = (const float*)d_in[3];
    const float* lin_in    = (const float*)d_in[4];
    const float* alpha_in  = (const float*)d_in[5];
    const float* a0_wqkv   = (const float*)d_in[6];
    const float* a0_bn_qkv = (const float*)d_in[7];
    const float* a0_bn_sim = (const float*)d_in[8];
    const float* a0_bn_out = (const float*)d_in[9];
    const float* a0_rel    = (const float*)d_in[10];
    const float* a1_wqkv   = (const float*)d_in[11];
    const float* a1_bn_qkv = (const float*)d_in[12];
    const float* a1_bn_sim = (const float*)d_in[13];
    const float* a1_bn_out = (const float*)d_in[14];
    const float* a1_rel    = (const float*)d_in[15];
    const float* w_out     = (const float*)d_in[16];
    const float* bn_out    = (const float*)d_in[17];
    const float* lin_out   = (const float*)d_in[18];
    const float* w_res     = (const float*)d_in[19];
    const float* alpha_fin = (const float*)d_in[20];
    float* out = (float*)d_out;

    float *yb, *ytb, *qkvb, *pyb, *pxb, *sbb;
    cudaGetSymbolAddress((void**)&yb,   g_y);
    cudaGetSymbolAddress((void**)&ytb,  g_yt);
    cudaGetSymbolAddress((void**)&qkvb, g_qkv);
    cudaGetSymbolAddress((void**)&pyb,  g_py);
    cudaGetSymbolAddress((void**)&pxb,  g_px);
    cudaGetSymbolAddress((void**)&sbb,  g_sb);

    cudaFuncSetAttribute(attn_kernel, cudaFuncAttributeMaxDynamicSharedMemorySize,
                         ATTN_SMEM_BYTES);

    dim3 tgrid(2, 2, NB * CO);
    dim3 tblk(32, 8);

    // 1. latent-conditioned scale/bias
    sb_kernel<<<16, 256>>>(latent, lin_in, lin_out, sbb);

    // 2. y = prelu(cbn(conv1x1(w_in, x)))
    {
        dim3 g(NP_FULL / 128, CO / 128, NB);
        conv1x1_tc_kernel<<<g, 256>>>(w_in, x, yb, CINC, CO, NP_FULL,
                                      bn_in, sbb, alpha_in, 0);
    }

    // 3. transpose; qkv conv a0; attn0
    transpose_kernel<<<tgrid, tblk>>>(yb, ytb);
    {
        dim3 g(NP_FULL / 128, (2 * CO) / 128, NB);
        conv1x1_tc_kernel<<<g, 256>>>(a0_wqkv, ytb, qkvb, CO, 2 * CO, NP_FULL,
                                      a0_bn_qkv, nullptr, nullptr, 1);
        dim3 ga(256, NG);
        attn_kernel<<<ga, 512, ATTN_SMEM_BYTES>>>(qkvb, yb, a0_rel,
                                                  a0_bn_sim, a0_bn_out);
    }

    // 4. transpose; qkv conv a1; attn1
    transpose_kernel<<<tgrid, tblk>>>(yb, ytb);
    {
        dim3 g(NP_FULL / 128, (2 * CO) / 128, NB);
        conv1x1_tc_kernel<<<g, 256>>>(a1_wqkv, ytb, qkvb, CO, 2 * CO, NP_FULL,
                                      a1_bn_qkv, nullptr, nullptr, 1);
        dim3 ga(256, NG);
        attn_kernel<<<ga, 512, ATTN_SMEM_BYTES>>>(qkvb, yb, a1_rel,
                                                  a1_bn_sim, a1_bn_out);
    }

    // 5. merged pools
    pool2_kernel<<<(POOL_TOTAL + 255) / 256, 256>>>(yb, pyb, x, pxb);

    // 6. final (tensor-core, cbn folded into A, pooled inputs)
    {
        dim3 g(NP_HALF / 128, CO / 128, NB);
        final_tc_kernel<<<g, 256>>>(w_out, pyb, w_res, pxb, out,
                                    bn_out, sbb + 2048, alpha_fin);
    }
}